// round 2
// baseline (speedup 1.0000x reference)
#include <cuda_runtime.h>
#include <cstdint>

// Problem constants
#define B_SZ   1024
#define F_SZ   784
#define OUT_F  1024
#define OR_T   32
#define AND_T  16
#define NLIT   (1 + 2 * F_SZ)   // 1569 literals
#define NBG    (B_SZ / 32)      // 32 batch-groups

// Literal table: T[idx][bg] = 32-bit mask over batches bg*32..bg*32+31
// idx 0 -> constant true; 1..784 -> x[f]; 785..1568 -> !x[f]
// Size: 1569 * 32 * 4 B ~= 200 KB (device global scratch, L2-resident)
__device__ uint32_t g_T[NLIT * NBG];

// ---------------------------------------------------------------------------
// Pack kernel: 32 blocks (one per batch-group), 256 threads (8 warps).
// Warp lane = batch-within-group; ballot packs 32 batches into one mask.
// ---------------------------------------------------------------------------
__global__ void pack_kernel(const float* __restrict__ x) {
    const int bg   = blockIdx.x;          // 0..31
    const int lane = threadIdx.x & 31;
    const int wid  = threadIdx.x >> 5;    // 0..7

    if (threadIdx.x == 0) {
        g_T[0 * NBG + bg] = 0xFFFFFFFFu;  // constant-true literal
    }

    const size_t row = (size_t)(bg * 32 + lane) * F_SZ;
    for (int f = wid; f < F_SZ; f += 8) {
        float v = x[row + f];
        uint32_t m = __ballot_sync(0xFFFFFFFFu, v != 0.0f);
        if (lane == 0) {
            g_T[(size_t)(1 + f) * NBG + bg]        = m;
            g_T[(size_t)(1 + F_SZ + f) * NBG + bg] = ~m;
        }
    }
}

// ---------------------------------------------------------------------------
// Main kernel: 128 blocks x 256 threads. Each warp owns ONE output feature;
// lane = batch-group. All lanes share the same weight indices per term, so
// table loads g_T[idx*32 + lane] are fully coalesced 128B transactions.
// ---------------------------------------------------------------------------
#define OUTS_PER_BLOCK 8

__global__ __launch_bounds__(256) void logic_kernel(
    const int* __restrict__ weights, float* __restrict__ out) {

    __shared__ uint32_t sw[OUTS_PER_BLOCK * OR_T * AND_T];  // 16 KB of weights
    __shared__ uint32_t resbuf[OUTS_PER_BLOCK][NBG];        // per-warp results

    const int tid   = threadIdx.x;
    const int oBase = blockIdx.x * OUTS_PER_BLOCK;

    // Cooperative coalesced load of this block's weights into smem
    {
        const uint4* src = (const uint4*)(weights + (size_t)oBase * OR_T * AND_T);
        uint4* dst = (uint4*)sw;
        const int nvec = OUTS_PER_BLOCK * OR_T * AND_T / 4;  // 1024
        for (int i = tid; i < nvec; i += 256) dst[i] = src[i];
    }
    __syncthreads();

    const int wi   = tid >> 5;   // which output within block
    const int lane = tid & 31;   // batch-group

    const uint32_t* tw = sw + wi * (OR_T * AND_T);

    uint32_t res = 0;
    #pragma unroll 4
    for (int t = 0; t < OR_T; ++t) {
        uint32_t m   = 0xFFFFFFFFu;
        uint32_t orw = 0;
        #pragma unroll
        for (int k = 0; k < AND_T; ++k) {
            uint32_t idx = tw[t * AND_T + k];   // uniform across warp
            orw |= idx;
            m &= g_T[(size_t)idx * NBG + lane]; // coalesced 128B LDG
        }
        if (orw != 0) res |= m;                 // all-zero term => masked off
    }

    resbuf[wi][lane] = res;
    __syncthreads();

    // Transposed store: for each batch, write this block's 8 output booleans
    // as float 0.0/1.0 (output dtype is float32). Two float4 stores = 32B,
    // contiguous & coalesced across threads.
    for (int b = tid; b < B_SZ; b += 256) {
        const int bg = b >> 5;
        const int j  = b & 31;
        float4 v0, v1;
        v0.x = (float)((resbuf[0][bg] >> j) & 1u);
        v0.y = (float)((resbuf[1][bg] >> j) & 1u);
        v0.z = (float)((resbuf[2][bg] >> j) & 1u);
        v0.w = (float)((resbuf[3][bg] >> j) & 1u);
        v1.x = (float)((resbuf[4][bg] >> j) & 1u);
        v1.y = (float)((resbuf[5][bg] >> j) & 1u);
        v1.z = (float)((resbuf[6][bg] >> j) & 1u);
        v1.w = (float)((resbuf[7][bg] >> j) & 1u);
        float4* dst = (float4*)(out + (size_t)b * OUT_F + oBase);
        dst[0] = v0;
        dst[1] = v1;
    }
}

// ---------------------------------------------------------------------------
extern "C" void kernel_launch(void* const* d_in, const int* in_sizes, int n_in,
                              void* d_out, int out_size) {
    const float* x       = (const float*)d_in[0];   // (1024, 784) float32
    const int*   weights = (const int*)d_in[1];     // (1024, 32, 16) int32
    float*       out     = (float*)d_out;           // (1024, 1024) float32 (bool-valued)

    pack_kernel<<<NBG, 256>>>(x);
    logic_kernel<<<OUT_F / OUTS_PER_BLOCK, 256>>>(weights, out);
}

// round 3
// speedup vs baseline: 2.2988x; 2.2988x over previous
#include <cuda_runtime.h>
#include <cstdint>

// Problem constants
#define B_SZ   1024
#define F_SZ   784
#define OUT_F  1024
#define OR_T   32
#define AND_T  16
#define NLIT   (1 + 2 * F_SZ)   // 1569 literals
#define NBG    (B_SZ / 32)      // 32 batch-groups
#define TBL_WORDS (NLIT * NBG)  // 50208 words ~= 200 KB

#define OUTS_PER_BLOCK 8
#define W_WORDS (OUTS_PER_BLOCK * OR_T * AND_T)   // 4096
#define SMEM_WORDS (TBL_WORDS + W_WORDS + OUTS_PER_BLOCK * NBG)
#define SMEM_BYTES (SMEM_WORDS * 4)               // 218,240 B (< 227 KB opt-in)

// Literal table in global: T[idx][bg]; idx 0 = const-true, 1..784 = x[f],
// 785..1568 = !x[f]. Built by pack_kernel, consumed (via smem) by logic_kernel.
__device__ uint32_t g_T[TBL_WORDS];

// ---------------------------------------------------------------------------
// Pack kernel: grid (25, 32) = (feature-tile, batch-group), 128 threads.
// Coalesced 32x32 tile load -> smem transpose -> ballot per feature.
// ---------------------------------------------------------------------------
__global__ __launch_bounds__(128) void pack_kernel(const float* __restrict__ x) {
    __shared__ float tile[32][33];            // +1 pad: conflict-free columns

    const int ft  = blockIdx.x;               // 0..24 (feature tile)
    const int bg  = blockIdx.y;               // 0..31 (batch group)
    const int tid = threadIdx.x;
    const int f0  = ft * 32;

    // Load 32 batches x 32 features, coalesced along features
    const int c  = tid & 31;
    const int r0 = tid >> 5;                  // 4 rows per pass
    #pragma unroll
    for (int r = r0; r < 32; r += 4) {
        const int f = f0 + c;
        float v = (f < F_SZ) ? x[(size_t)(bg * 32 + r) * F_SZ + f] : 0.0f;
        tile[r][c] = v;
    }
    __syncthreads();

    // Warp w handles features f0+w, f0+w+4, ... ; lane = batch-within-group
    const int lane = tid & 31;
    const int w    = tid >> 5;
    #pragma unroll
    for (int ff = w; ff < 32; ff += 4) {
        const int f = f0 + ff;
        if (f >= F_SZ) break;                 // warp-uniform
        uint32_t m = __ballot_sync(0xFFFFFFFFu, tile[lane][ff] != 0.0f);
        if (lane == 0) {
            g_T[(size_t)(1 + f) * NBG + bg]        = m;
            g_T[(size_t)(1 + F_SZ + f) * NBG + bg] = ~m;
        }
    }
    if (ft == 0 && tid == 0) g_T[bg] = 0xFFFFFFFFu;   // const-true literal
}

// ---------------------------------------------------------------------------
// Logic kernel: 128 blocks x 256 threads, full literal table in shared memory.
// Warp = one output feature, lane = batch-group; sT[idx*32+lane] is a
// conflict-free LDS (consecutive words across lanes).
// ---------------------------------------------------------------------------
__global__ __launch_bounds__(256) void logic_kernel(
    const int* __restrict__ weights, float* __restrict__ out) {

    extern __shared__ uint32_t smem[];
    uint32_t* sT   = smem;                    // 50208 words: literal table
    uint32_t* sw   = smem + TBL_WORDS;        // 4096 words: this block's weights
    uint32_t* resb = sw + W_WORDS;            // 256 words: per-warp results

    const int tid   = threadIdx.x;
    const int oBase = blockIdx.x * OUTS_PER_BLOCK;

    // Fill smem: literal table (uint4, coalesced) + weights
    {
        const uint4* gsrc = (const uint4*)g_T;
        uint4* sdst = (uint4*)sT;
        for (int i = tid; i < TBL_WORDS / 4; i += 256) sdst[i] = gsrc[i];

        const uint4* wsrc = (const uint4*)(weights + (size_t)oBase * OR_T * AND_T);
        uint4* wdst = (uint4*)sw;
        for (int i = tid; i < W_WORDS / 4; i += 256) wdst[i] = wsrc[i];
    }
    __syncthreads();

    const int wi   = tid >> 5;                // output within block
    const int lane = tid & 31;                // batch-group
    const uint32_t* tw = sw + wi * (OR_T * AND_T);

    uint32_t res = 0;
    #pragma unroll 2
    for (int t = 0; t < OR_T; ++t) {
        uint32_t m   = 0xFFFFFFFFu;
        uint32_t orw = 0;
        #pragma unroll
        for (int k = 0; k < AND_T; ++k) {
            const uint32_t idx = tw[t * AND_T + k];   // uniform across warp
            orw |= idx;
            m &= sT[idx * NBG + lane];                // conflict-free LDS
        }
        if (orw != 0) res |= m;                       // all-zero term masked off
    }

    resb[wi * NBG + lane] = res;
    __syncthreads();

    // Transposed store: per batch, 8 contiguous floats (two float4 = 32B)
    for (int b = tid; b < B_SZ; b += 256) {
        const int bg = b >> 5;
        const int j  = b & 31;
        float4 v0, v1;
        v0.x = (float)((resb[0 * NBG + bg] >> j) & 1u);
        v0.y = (float)((resb[1 * NBG + bg] >> j) & 1u);
        v0.z = (float)((resb[2 * NBG + bg] >> j) & 1u);
        v0.w = (float)((resb[3 * NBG + bg] >> j) & 1u);
        v1.x = (float)((resb[4 * NBG + bg] >> j) & 1u);
        v1.y = (float)((resb[5 * NBG + bg] >> j) & 1u);
        v1.z = (float)((resb[6 * NBG + bg] >> j) & 1u);
        v1.w = (float)((resb[7 * NBG + bg] >> j) & 1u);
        float4* dst = (float4*)(out + (size_t)b * OUT_F + oBase);
        dst[0] = v0;
        dst[1] = v1;
    }
}

// ---------------------------------------------------------------------------
extern "C" void kernel_launch(void* const* d_in, const int* in_sizes, int n_in,
                              void* d_out, int out_size) {
    const float* x       = (const float*)d_in[0];   // (1024, 784) float32
    const int*   weights = (const int*)d_in[1];     // (1024, 32, 16) int32
    float*       out     = (float*)d_out;           // (1024, 1024) float32

    // Opt-in to large dynamic smem (idempotent; not a stream op -> capture-safe)
    cudaFuncSetAttribute(logic_kernel,
                         cudaFuncAttributeMaxDynamicSharedMemorySize, SMEM_BYTES);

    dim3 pgrid(25, 32);
    pack_kernel<<<pgrid, 128>>>(x);
    logic_kernel<<<OUT_F / OUTS_PER_BLOCK, 256, SMEM_BYTES>>>(weights, out);
}

// round 4
// speedup vs baseline: 2.9677x; 1.2909x over previous
#include <cuda_runtime.h>
#include <cstdint>

// Problem constants
#define B_SZ   1024
#define F_SZ   784
#define OUT_F  1024
#define OR_T   32
#define AND_T  16
#define NLIT   (1 + 2 * F_SZ)   // 1569 literals
#define NBG    (B_SZ / 32)      // 32 batch-groups
#define TBL_WORDS (NLIT * NBG)  // 50208 words = 200832 B
#define TBL_BYTES (TBL_WORDS * 4)

#define OUTS_PER_BLOCK 8
#define NTHREADS 512
#define W_WORDS (OUTS_PER_BLOCK * OR_T * AND_T)     // 4096 words = 16 KB
// smem layout (words): [table | weights | results(8*2*32) | pad | mbar(2 words)]
#define RES_WORDS (OUTS_PER_BLOCK * 2 * NBG)        // 512
#define MBAR_OFF_W (TBL_WORDS + W_WORDS + RES_WORDS + 4)  // keep 16B aligned
#define SMEM_BYTES ((MBAR_OFF_W + 4) * 4)

// Literal table in global, 16B-aligned for TMA bulk copy.
__device__ __align__(16) uint32_t g_T[TBL_WORDS];

// ---------------------------------------------------------------------------
// Pack kernel: grid (25, 32), 128 threads. Coalesced tile load -> smem
// transpose -> ballot per feature.
// ---------------------------------------------------------------------------
__global__ __launch_bounds__(128) void pack_kernel(const float* __restrict__ x) {
    __shared__ float tile[32][33];

    const int ft  = blockIdx.x;               // feature tile 0..24
    const int bg  = blockIdx.y;               // batch group 0..31
    const int tid = threadIdx.x;
    const int f0  = ft * 32;

    const int c  = tid & 31;
    const int r0 = tid >> 5;
    #pragma unroll
    for (int r = r0; r < 32; r += 4) {
        const int f = f0 + c;
        tile[r][c] = (f < F_SZ) ? x[(size_t)(bg * 32 + r) * F_SZ + f] : 0.0f;
    }
    __syncthreads();

    const int lane = tid & 31;
    const int w    = tid >> 5;
    #pragma unroll
    for (int ff = w; ff < 32; ff += 4) {
        const int f = f0 + ff;
        if (f >= F_SZ) break;
        uint32_t m = __ballot_sync(0xFFFFFFFFu, tile[lane][ff] != 0.0f);
        if (lane == 0) {
            g_T[(size_t)(1 + f) * NBG + bg]        = m;
            g_T[(size_t)(1 + F_SZ + f) * NBG + bg] = ~m;
        }
    }
    if (ft == 0 && tid == 0) g_T[bg] = 0xFFFFFFFFu;   // const-true literal
}

// ---------------------------------------------------------------------------
// Logic kernel: 128 blocks x 512 threads.
//  - TMA bulk-copies the 200KB literal table into smem (8 chunks, 1 mbarrier)
//    while the warps load this block's weights.
//  - Warps 2w, 2w+1 co-own output w; each handles 16 of 32 OR-terms.
// ---------------------------------------------------------------------------
__global__ __launch_bounds__(NTHREADS) void logic_kernel(
    const int* __restrict__ weights, float* __restrict__ out) {

    extern __shared__ uint32_t smem[];
    uint32_t* sT   = smem;
    uint32_t* sw   = smem + TBL_WORDS;
    uint32_t* resb = sw + W_WORDS;
    uint32_t  mbar_addr;
    {
        uint64_t* mb64 = (uint64_t*)(smem + MBAR_OFF_W);
        asm("{ .reg .u64 t; cvta.to.shared.u64 t, %1; cvt.u32.u64 %0, t; }"
            : "=r"(mbar_addr) : "l"((void*)mb64));
    }

    const int tid   = threadIdx.x;
    const int oBase = blockIdx.x * OUTS_PER_BLOCK;

    // Init mbarrier (thread 0)
    if (tid == 0) {
        asm volatile("mbarrier.init.shared.b64 [%0], 1;" :: "r"(mbar_addr) : "memory");
    }
    __syncthreads();

    // Thread 0: expect full table, issue 8 bulk copies (UBLKCP)
    if (tid == 0) {
        asm volatile("mbarrier.arrive.expect_tx.shared.b64 _, [%0], %1;"
                     :: "r"(mbar_addr), "r"((uint32_t)TBL_BYTES) : "memory");
        const char* gsrc = (const char*)g_T;
        uint32_t sdst;
        asm("{ .reg .u64 t; cvta.to.shared.u64 t, %1; cvt.u32.u64 %0, t; }"
            : "=r"(sdst) : "l"((void*)sT));
        const uint32_t chunk = TBL_BYTES / 8;   // 25104 B, multiple of 16
        #pragma unroll
        for (int i = 0; i < 8; ++i) {
            asm volatile(
                "cp.async.bulk.shared::cta.global.mbarrier::complete_tx::bytes "
                "[%0], [%1], %2, [%3];"
                :: "r"(sdst + i * chunk), "l"(gsrc + i * chunk),
                   "r"(chunk), "r"(mbar_addr) : "memory");
        }
    }

    // Meanwhile: all 512 threads load this block's weights into smem
    {
        const uint4* wsrc = (const uint4*)(weights + (size_t)oBase * OR_T * AND_T);
        uint4* wdst = (uint4*)sw;
        #pragma unroll
        for (int i = tid; i < W_WORDS / 4; i += NTHREADS) wdst[i] = wsrc[i];
    }
    __syncthreads();   // weights visible; also orders mbarrier init for all

    // Wait for the table DMA
    {
        uint32_t done;
        asm volatile(
            "{\n\t.reg .pred p;\n\t"
            "mbarrier.try_wait.parity.acquire.cta.shared::cta.b64 p, [%1], 0;\n\t"
            "selp.b32 %0, 1, 0, p;\n\t}"
            : "=r"(done) : "r"(mbar_addr) : "memory");
        if (!done) {
            asm volatile(
                "{\n\t.reg .pred P1;\n\t"
                "WL_%=:\n\t"
                "mbarrier.try_wait.parity.acquire.cta.shared::cta.b64 P1, [%0], 0, 0x989680;\n\t"
                "@P1 bra.uni WD_%=;\n\t"
                "bra.uni WL_%=;\n\t"
                "WD_%=:\n\t}"
                :: "r"(mbar_addr) : "memory");
        }
    }

    // Gather: warp pair (2w, 2w+1) -> output w; half h handles terms h*16..h*16+15
    const int wid  = tid >> 5;                 // 0..15
    const int lane = tid & 31;                 // batch-group
    const int wi   = wid >> 1;                 // output within block
    const int h    = wid & 1;                  // OR-term half

    const uint32_t* tw = sw + wi * (OR_T * AND_T) + h * (16 * AND_T);

    uint32_t res = 0;
    #pragma unroll 4
    for (int t = 0; t < 16; ++t) {
        uint32_t m   = 0xFFFFFFFFu;
        uint32_t orw = 0;
        #pragma unroll
        for (int k = 0; k < AND_T; ++k) {
            const uint32_t idx = tw[t * AND_T + k];   // uniform broadcast LDS
            orw |= idx;
            m &= sT[idx * NBG + lane];                // conflict-free LDS
        }
        if (orw != 0) res |= m;
    }
    resb[(wi * 2 + h) * NBG + lane] = res;
    __syncthreads();

    // Store: per batch, 8 contiguous floats (two float4), combining halves
    #pragma unroll
    for (int b = tid; b < B_SZ; b += NTHREADS) {
        const int bg = b >> 5;
        const int j  = b & 31;
        float4 v0, v1;
        #define GETBIT(ow) ((((resb[(ow)*2*NBG + bg] | resb[((ow)*2+1)*NBG + bg]) >> j) & 1u))
        v0.x = (float)GETBIT(0); v0.y = (float)GETBIT(1);
        v0.z = (float)GETBIT(2); v0.w = (float)GETBIT(3);
        v1.x = (float)GETBIT(4); v1.y = (float)GETBIT(5);
        v1.z = (float)GETBIT(6); v1.w = (float)GETBIT(7);
        #undef GETBIT
        float4* dst = (float4*)(out + (size_t)b * OUT_F + oBase);
        dst[0] = v0;
        dst[1] = v1;
    }
}

// ---------------------------------------------------------------------------
extern "C" void kernel_launch(void* const* d_in, const int* in_sizes, int n_in,
                              void* d_out, int out_size) {
    const float* x       = (const float*)d_in[0];   // (1024, 784) float32
    const int*   weights = (const int*)d_in[1];     // (1024, 32, 16) int32
    float*       out     = (float*)d_out;           // (1024, 1024) float32

    cudaFuncSetAttribute(logic_kernel,
                         cudaFuncAttributeMaxDynamicSharedMemorySize, SMEM_BYTES);

    dim3 pgrid(25, 32);
    pack_kernel<<<pgrid, 128>>>(x);
    logic_kernel<<<OUT_F / OUTS_PER_BLOCK, NTHREADS, SMEM_BYTES>>>(weights, out);
}